// round 15
// baseline (speedup 1.0000x reference)
#include <cuda_runtime.h>
#include <cuda_fp16.h>
#include <cstdint>
#include <math.h>

#define DIM 4096
#define NH  32
#define NKV 8
#define HD  128
#define B_  2
#define S_  2048
#define T_  (B_*S_)          // 4096 tokens
#define NREP 4
#define NQKV 6144            // NH*HD + 2*NKV*HD
#define NWALL 10240          // NQKV + DIM (all weights)

// ---------------- scratch (device globals; no cudaMalloc allowed) ----------
__device__ __half g_xh[(size_t)T_ * DIM];
__device__ __half g_xl[(size_t)T_ * DIM];
__device__ __half g_oh[(size_t)T_ * DIM];
__device__ __half g_ol[(size_t)T_ * DIM];
__device__ __half g_qh[(size_t)T_ * NH * HD];
__device__ __half g_ql[(size_t)T_ * NH * HD];
__device__ __half g_kh[(size_t)T_ * NKV * HD];
__device__ __half g_kl[(size_t)T_ * NKV * HD];
__device__ __half g_vh[(size_t)T_ * NKV * HD];
__device__ __half g_wqkv[(size_t)NQKV * DIM];   // [wq | wk | wv] transposed
__device__ __half g_wot[(size_t)DIM * DIM];

// ---------------- low-level helpers (sm_103 base-target safe) --------------
__device__ __forceinline__ uint32_t smem_u32(const void* p) {
    uint32_t a;
    asm("{ .reg .u64 t; cvta.to.shared.u64 t, %1; cvt.u32.u64 %0, t; }"
        : "=r"(a) : "l"(p));
    return a;
}
__device__ __forceinline__ void cp_async16(uint32_t dst, const void* src) {
    asm volatile("cp.async.cg.shared.global [%0], [%1], 16;"
                 :: "r"(dst), "l"(src));
}
#define CP_COMMIT() asm volatile("cp.async.commit_group;" ::: "memory")
#define CP_WAIT(n)  asm volatile("cp.async.wait_group %0;" :: "n"(n) : "memory")

__device__ __forceinline__ void ldsm4(uint32_t& r0, uint32_t& r1,
                                      uint32_t& r2, uint32_t& r3, uint32_t a) {
    asm volatile("ldmatrix.sync.aligned.m8n8.x4.shared.b16 {%0,%1,%2,%3}, [%4];"
                 : "=r"(r0), "=r"(r1), "=r"(r2), "=r"(r3) : "r"(a));
}
__device__ __forceinline__ void ldsm4t(uint32_t& r0, uint32_t& r1,
                                       uint32_t& r2, uint32_t& r3, uint32_t a) {
    asm volatile("ldmatrix.sync.aligned.m8n8.x4.trans.shared.b16 {%0,%1,%2,%3}, [%4];"
                 : "=r"(r0), "=r"(r1), "=r"(r2), "=r"(r3) : "r"(a));
}
__device__ __forceinline__ void mma_f16(float* c, const uint32_t* a,
                                        const uint32_t* b) {
    asm volatile(
        "mma.sync.aligned.m16n8k16.row.col.f32.f16.f16.f32 "
        "{%0,%1,%2,%3}, {%4,%5,%6,%7}, {%8,%9}, {%0,%1,%2,%3};"
        : "+f"(c[0]), "+f"(c[1]), "+f"(c[2]), "+f"(c[3])
        : "r"(a[0]), "r"(a[1]), "r"(a[2]), "r"(a[3]), "r"(b[0]), "r"(b[1]));
}

// ---------------- split-fp16 conversion -------------------------------------
__device__ __forceinline__ void split_f16(float x, __half& h, __half& l)
{
    h = __float2half_rn(x);
    l = __float2half_rn(x - __half2float(h));
}
__device__ __forceinline__ uint32_t pack_f16(__half lo, __half hi)
{
    __half2 v;
    v.x = lo; v.y = hi;
    return *(uint32_t*)&v;
}

__global__ void conv_split_kernel(const float* __restrict__ X,
                                  __half* __restrict__ H,
                                  __half* __restrict__ L, int n4)
{
    int i = blockIdx.x * blockDim.x + threadIdx.x;
    if (i >= n4) return;
    float4 v = *(const float4*)(X + (size_t)i * 4);
    __half h[4], l[4];
    split_f16(v.x, h[0], l[0]);
    split_f16(v.y, h[1], l[1]);
    split_f16(v.z, h[2], l[2]);
    split_f16(v.w, h[3], l[3]);
    *(uint2*)(H + (size_t)i * 4) = *(uint2*)h;
    *(uint2*)(L + (size_t)i * 4) = *(uint2*)l;
}

// merged transpose+convert of wq|wk|wv|wo into g_wqkv / g_wot (one launch)
__global__ void wconv_all_kernel(const float* __restrict__ wq,
                                 const float* __restrict__ wk,
                                 const float* __restrict__ wv,
                                 const float* __restrict__ wo)
{
    __shared__ float t[32][33];
    const int c0 = blockIdx.x * 32;   // combined column tile (0..NWALL-1)
    const int k0 = blockIdx.y * 32;
    const int tx = threadIdx.x;
    const int ty = threadIdx.y;

    const float* W;
    __half* Hd;
    int nloc, Nsrc, dcol;
    if (c0 < NH * HD) {
        W = wq; nloc = c0; Nsrc = NH * HD; Hd = g_wqkv; dcol = c0;
    } else if (c0 < NH * HD + NKV * HD) {
        W = wk; nloc = c0 - NH * HD; Nsrc = NKV * HD; Hd = g_wqkv; dcol = c0;
    } else if (c0 < NQKV) {
        W = wv; nloc = c0 - NH * HD - NKV * HD; Nsrc = NKV * HD; Hd = g_wqkv; dcol = c0;
    } else {
        W = wo; nloc = c0 - NQKV; Nsrc = DIM; Hd = g_wot; dcol = c0 - NQKV;
    }

    #pragma unroll
    for (int i = 0; i < 4; i++)
        t[ty + 8 * i][tx] = W[(size_t)(k0 + ty + 8 * i) * Nsrc + nloc + tx];
    __syncthreads();
    #pragma unroll
    for (int i = 0; i < 4; i++) {
        float v = t[tx][ty + 8 * i];
        Hd[(size_t)(dcol + ty + 8 * i) * DIM + k0 + tx] = __float2half_rn(v);
    }
}

// ---------------- HMMA 2-pass split-fp16 GEMM (128x256 tile, BK=64) --------
#define GK       DIM
#define NCH2     (GK / 64)          // 32 double-chunks
#define A_H_OFF  0
#define A_L_OFF  16384
#define B_OFF    32768
#define STAGEB   65536              // Ah(16K) + Al(16K) + B(32K)
#define GEMM_SMEM (2 * STAGEB)      // 128 KB

__device__ __forceinline__ uint32_t chunk_offA(int row, int kg) {
    return (uint32_t)(kg * 128 + ((row + 2 * kg) & 127)) * 16u;
}
__device__ __forceinline__ uint32_t chunk_offB(int row, int kg) {
    return (uint32_t)(kg * 256 + ((row + 2 * kg) & 255)) * 16u;
}

#define ATT_SCALE 0.08838834764831843f   // 1/sqrt(128), folded into Q

template<int MODE>
__global__ __launch_bounds__(512, 1) void gemm_hmma(
    const __half* __restrict__ Ah, const __half* __restrict__ Al,
    const __half* __restrict__ B,
    float* __restrict__ C, int N,
    const float* __restrict__ fcos, const float* __restrict__ fsin)
{
    extern __shared__ char smg[];
    const uint32_t sbase = smem_u32(smg);

    const int tid = threadIdx.x;
    const int wid = tid >> 5;
    const int lid = tid & 31;
    const int wm  = wid >> 2;      // 0..3 (32 rows each)
    const int wn  = wid & 3;       // 0..3 (64 cols each)
    const int m0  = blockIdx.y * 128;
    const int n0  = blockIdx.x * 256;

    const int lkg = tid & 7;       // 0..7 (16B k-group within BK=64)
    const int lr  = tid >> 3;      // 0..63

    auto load_stage = [&](int stage, int kc2) {
        const uint32_t sb = sbase + stage * STAGEB;
        const size_t koff = (size_t)kc2 * 64 + lkg * 8;
        #pragma unroll
        for (int i = 0; i < 2; i++) {
            const int r = lr + i * 64;
            const uint32_t co = chunk_offA(r, lkg);
            const size_t ga = (size_t)(m0 + r) * GK + koff;
            cp_async16(sb + A_H_OFF + co, Ah + ga);
            cp_async16(sb + A_L_OFF + co, Al + ga);
        }
        #pragma unroll
        for (int i = 0; i < 4; i++) {
            const int r = lr + i * 64;
            const uint32_t co = chunk_offB(r, lkg);
            const size_t gb = (size_t)(n0 + r) * GK + koff;
            cp_async16(sb + B_OFF + co, B + gb);
        }
    };

    float acc[2][8][4];
    #pragma unroll
    for (int i = 0; i < 2; i++)
        #pragma unroll
        for (int j = 0; j < 8; j++)
            #pragma unroll
            for (int k = 0; k < 4; k++) acc[i][j][k] = 0.f;

    const int sel  = lid >> 3;
    const int lsub = lid & 7;
    const int a_mo = lsub + ((sel & 1) << 3);
    const int a_kg = sel >> 1;
    const int b_no = lsub + ((sel >> 1) << 3);
    const int b_kg = sel & 1;

    load_stage(0, 0); CP_COMMIT();

    for (int kc2 = 0; kc2 < NCH2; kc2++) {
        CP_WAIT(0);              // stage kc2 data complete (only group in flight)
        __syncthreads();         // visibility + buffer guard for prefetch below

        if (kc2 + 1 < NCH2) { load_stage((kc2 + 1) & 1, kc2 + 1); CP_COMMIT(); }

        const uint32_t sb = sbase + (kc2 & 1) * STAGEB;

        #pragma unroll
        for (int ks = 0; ks < 4; ks++) {
            const int kgA = ks * 2 + a_kg;
            const int kgB = ks * 2 + b_kg;

            uint32_t afh[2][4], afl[2][4];
            #pragma unroll
            for (int mt = 0; mt < 2; mt++) {
                const int m = wm * 32 + mt * 16 + a_mo;
                const uint32_t co = chunk_offA(m, kgA);
                ldsm4(afh[mt][0], afh[mt][1], afh[mt][2], afh[mt][3],
                      sb + A_H_OFF + co);
                ldsm4(afl[mt][0], afl[mt][1], afl[mt][2], afl[mt][3],
                      sb + A_L_OFF + co);
            }
            uint32_t bf[4][4];
            #pragma unroll
            for (int nt2 = 0; nt2 < 4; nt2++) {
                const int n = wn * 64 + nt2 * 16 + b_no;
                const uint32_t co = chunk_offB(n, kgB);
                ldsm4(bf[nt2][0], bf[nt2][1], bf[nt2][2], bf[nt2][3],
                      sb + B_OFF + co);
            }
            #pragma unroll
            for (int mt = 0; mt < 2; mt++)
                #pragma unroll
                for (int nt = 0; nt < 8; nt++) {
                    uint32_t b2[2] = { bf[nt >> 1][(nt & 1) << 1],
                                       bf[nt >> 1][((nt & 1) << 1) + 1] };
                    mma_f16(acc[mt][nt], afh[mt], b2);
                    mma_f16(acc[mt][nt], afl[mt], b2);
                }
        }
    }

    const int crow = lid >> 2;
    const int ccol = (lid & 3) * 2;

    if (MODE == 0) {
        #pragma unroll
        for (int mt = 0; mt < 2; mt++) {
            const int r0 = m0 + wm * 32 + mt * 16 + crow;
            #pragma unroll
            for (int nt = 0; nt < 8; nt++) {
                const int c0 = n0 + wn * 64 + nt * 8 + ccol;
                *(float2*)(C + (size_t)r0 * N + c0) =
                    make_float2(acc[mt][nt][0], acc[mt][nt][1]);
                *(float2*)(C + (size_t)(r0 + 8) * N + c0) =
                    make_float2(acc[mt][nt][2], acc[mt][nt][3]);
            }
        }
    } else {
        // fused RoPE + 1/sqrt(d) (Q only) + split-fp16 QKV epilogue
        const int seg = (n0 < NH * HD) ? 0 : (n0 < NH * HD + NKV * HD ? 1 : 2);
        __half* Hd;
        __half* Ld = nullptr;
        int colbase, rstride;
        if (seg == 0)      { Hd = g_qh; Ld = g_ql; colbase = n0;                rstride = NH * HD;  }
        else if (seg == 1) { Hd = g_kh; Ld = g_kl; colbase = n0 - NH * HD;      rstride = NKV * HD; }
        else               { Hd = g_vh;            colbase = n0 - NH * HD - NKV * HD; rstride = NKV * HD; }

        #pragma unroll
        for (int mt = 0; mt < 2; mt++) {
            const int r0 = m0 + wm * 32 + mt * 16 + crow;
            const int r1 = r0 + 8;
            const int s0 = r0 & (S_ - 1);
            const int s1 = r1 & (S_ - 1);
            #pragma unroll
            for (int nt = 0; nt < 8; nt++) {
                const int c = colbase + wn * 64 + nt * 8 + ccol;
                float v00 = acc[mt][nt][0], v01 = acc[mt][nt][1];
                float v10 = acc[mt][nt][2], v11 = acc[mt][nt][3];
                if (seg < 2) {
                    const int d = (c & (HD - 1)) >> 1;
                    const float c0v = fcos[s0 * (HD / 2) + d];
                    const float s0v = fsin[s0 * (HD / 2) + d];
                    const float c1v = fcos[s1 * (HD / 2) + d];
                    const float s1v = fsin[s1 * (HD / 2) + d];
                    float t00 = v00 * c0v - v01 * s0v;
                    float t01 = v00 * s0v + v01 * c0v;
                    float t10 = v10 * c1v - v11 * s1v;
                    float t11 = v10 * s1v + v11 * c1v;
                    v00 = t00; v01 = t01; v10 = t10; v11 = t11;
                    if (seg == 0) {
                        v00 *= ATT_SCALE; v01 *= ATT_SCALE;
                        v10 *= ATT_SCALE; v11 *= ATT_SCALE;
                    }
                }
                const size_t o0 = (size_t)r0 * rstride + c;
                const size_t o1 = (size_t)r1 * rstride + c;
                __half h0, l0, h1, l1;
                split_f16(v00, h0, l0);
                split_f16(v01, h1, l1);
                *(uint32_t*)(Hd + o0) = pack_f16(h0, h1);
                if (seg < 2) *(uint32_t*)(Ld + o0) = pack_f16(l0, l1);
                split_f16(v10, h0, l0);
                split_f16(v11, h1, l1);
                *(uint32_t*)(Hd + o1) = pack_f16(h0, h1);
                if (seg < 2) *(uint32_t*)(Ld + o1) = pack_f16(l0, l1);
            }
        }
    }
}

// ---------------- HMMA split-fp16 flash attention ---------------------------
// CTA: 128 q rows x one (b, head). 3-stage KV pipeline, Q cached in registers.
// Scale is pre-folded into Q by the GEMM epilogue.
#define SQH_OFF 0
#define SQL_OFF 32768
#define STG_OFF 65536
#define STG_SZ  49152              // Kh + Kl + Vh
#define KH_OFF  0
#define KL_OFF  16384
#define VH_OFF  32768
#define ATTN_SMEM (STG_OFF + 3 * STG_SZ)   // 208 KB

__device__ __forceinline__ uint32_t offq(int r, int c) {
    return (uint32_t)(c * 128 + ((r + 2 * c) & 127)) * 16u;
}
__device__ __forceinline__ uint32_t offkv(int r, int c) {
    return (uint32_t)(c * 64 + ((r + 2 * c) & 63)) * 16u;
}

__global__ __launch_bounds__(256, 1) void attn_hmma()
{
    extern __shared__ char sma[];
    const uint32_t sb = smem_u32(sma);

    const int tid = threadIdx.x;
    const int wid = tid >> 5;
    const int lid = tid & 31;
    const int bx  = gridDim.x - 1 - blockIdx.x;   // LPT: longest CTAs first
    const int h   = blockIdx.y;
    const int bz  = blockIdx.z;
    const int g   = h >> 2;
    const int qm0 = bx * 128;
    const int tb  = bz * S_;
    const int ntiles = 2 * (bx + 1);

    const int sel  = lid >> 3;
    const int lsub = lid & 7;
    const int a_r  = wid * 16 + lsub + ((sel & 1) << 3);
    const int a_co = sel >> 1;
    const int b_r  = lsub + ((sel >> 1) << 3);
    const int b_co = sel & 1;
    const int v_r  = lsub + ((sel & 1) << 3);
    const int v_co = sel >> 1;

    const int lc = tid & 15;
    const int lr = tid >> 4;

    // Q (once): 128 rows x 16 chunks x {h,l}
    {
        #pragma unroll
        for (int i = 0; i < 8; i++) {
            const int r = lr + 16 * i;
            const size_t go = ((size_t)(tb + qm0 + r) * NH + h) * HD + lc * 8;
            const uint32_t o = offq(r, lc);
            cp_async16(sb + SQH_OFF + o, g_qh + go);
            cp_async16(sb + SQL_OFF + o, g_ql + go);
        }
    }
    auto load_kv = [&](int stage, int t) {
        const uint32_t st = sb + STG_OFF + stage * STG_SZ;
        const int j0 = t * 64;
        #pragma unroll
        for (int i = 0; i < 4; i++) {
            const int r = lr + 16 * i;
            const size_t go = ((size_t)(tb + j0 + r) * NKV + g) * HD + lc * 8;
            const uint32_t o = offkv(r, lc);
            cp_async16(st + KH_OFF + o, g_kh + go);
            cp_async16(st + KL_OFF + o, g_kl + go);
            cp_async16(st + VH_OFF + o, g_vh + go);
        }
    };

    load_kv(0, 0); CP_COMMIT();                // group 0: Q + kv tile 0
    load_kv(1, 1); CP_COMMIT();                // group 1: kv tile 1 (ntiles >= 2)

    // wait for Q + tile0, cache Q fragments in registers
    CP_WAIT(1);
    __syncthreads();
    uint32_t qfh[8][4], qfl[8][4];
    #pragma unroll
    for (int kt = 0; kt < 8; kt++) {
        const uint32_t qo = offq(a_r, 2 * kt + a_co);
        ldsm4(qfh[kt][0], qfh[kt][1], qfh[kt][2], qfh[kt][3], sb + SQH_OFF + qo);
        ldsm4(qfl[kt][0], qfl[kt][1], qfl[kt][2], qfl[kt][3], sb + SQL_OFF + qo);
    }

    float o[16][4];
    #pragma unroll
    for (int i = 0; i < 16; i++)
        #pragma unroll
        for (int j = 0; j < 4; j++) o[i][j] = 0.f;
    float m_lo = -1e30f, m_hi = -1e30f;
    float l_lo = 0.f, l_hi = 0.f;
    const int row_lo = qm0 + wid * 16 + (lid >> 2);
    const int col_l  = (lid & 3) * 2;

    for (int t = 0; t < ntiles; t++) {
        if (t > 0) __syncthreads();            // buffer guard: readers of t-1 done

        // prefetch tile t+2 into stage (t+2)%3 (2-tile hiding distance)
        if (t + 2 < ntiles) load_kv((t + 2) % 3, t + 2);
        CP_COMMIT();                           // group t+2 (possibly empty)
        CP_WAIT(2);                            // group t complete
        __syncthreads();                       // cross-thread visibility of tile t

        const uint32_t stb = sb + STG_OFF + (t % 3) * STG_SZ;
        const bool masked = (t >= 2 * bx);
        const int j0 = t * 64;

        // ---- S = Q K^T (3-pass fp16; scale pre-folded into Q) ----
        float sacc[8][4];
        #pragma unroll
        for (int i = 0; i < 8; i++)
            #pragma unroll
            for (int j = 0; j < 4; j++) sacc[i][j] = 0.f;

        #pragma unroll
        for (int kt = 0; kt < 8; kt++) {
            uint32_t kh[4][4], kl[4][4];
            #pragma unroll
            for (int np = 0; np < 4; np++) {
                const uint32_t ko = offkv(np * 16 + b_r, 2 * kt + b_co);
                ldsm4(kh[np][0], kh[np][1], kh[np][2], kh[np][3],
                      stb + KH_OFF + ko);
                ldsm4(kl[np][0], kl[np][1], kl[np][2], kl[np][3],
                      stb + KL_OFF + ko);
            }
            #pragma unroll
            for (int nt = 0; nt < 8; nt++) {
                uint32_t bh[2] = { kh[nt >> 1][(nt & 1) << 1],
                                   kh[nt >> 1][((nt & 1) << 1) + 1] };
                uint32_t bl[2] = { kl[nt >> 1][(nt & 1) << 1],
                                   kl[nt >> 1][((nt & 1) << 1) + 1] };
                mma_f16(sacc[nt], qfh[kt], bh);
                mma_f16(sacc[nt], qfl[kt], bh);
                mma_f16(sacc[nt], qfh[kt], bl);
            }
        }

        // ---- causal mask (scale already applied via Q) ----
        if (masked) {
            #pragma unroll
            for (int nt = 0; nt < 8; nt++) {
                const int c0 = j0 + nt * 8 + col_l;
                sacc[nt][0] = (c0     <= row_lo)     ? sacc[nt][0] : -1e30f;
                sacc[nt][1] = (c0 + 1 <= row_lo)     ? sacc[nt][1] : -1e30f;
                sacc[nt][2] = (c0     <= row_lo + 8) ? sacc[nt][2] : -1e30f;
                sacc[nt][3] = (c0 + 1 <= row_lo + 8) ? sacc[nt][3] : -1e30f;
            }
        }

        // ---- online softmax ----
        float mx_lo = -1e30f, mx_hi = -1e30f;
        #pragma unroll
        for (int nt = 0; nt < 8; nt++) {
            mx_lo = fmaxf(mx_lo, fmaxf(sacc[nt][0], sacc[nt][1]));
            mx_hi = fmaxf(mx_hi, fmaxf(sacc[nt][2], sacc[nt][3]));
        }
        #pragma unroll
        for (int off = 1; off < 4; off <<= 1) {
            mx_lo = fmaxf(mx_lo, __shfl_xor_sync(0xffffffffu, mx_lo, off));
            mx_hi = fmaxf(mx_hi, __shfl_xor_sync(0xffffffffu, mx_hi, off));
        }
        const float mn_lo = fmaxf(m_lo, mx_lo);
        const float mn_hi = fmaxf(m_hi, mx_hi);
        const float al_lo = __expf(m_lo - mn_lo);
        const float al_hi = __expf(m_hi - mn_hi);
        m_lo = mn_lo; m_hi = mn_hi;

        float sum_lo = 0.f, sum_hi = 0.f;
        uint32_t aph[4][4];
        #pragma unroll
        for (int kt2 = 0; kt2 < 4; kt2++) {
            float p[2][4];
            #pragma unroll
            for (int half = 0; half < 2; half++) {
                const int nt = 2 * kt2 + half;
                p[half][0] = __expf(sacc[nt][0] - mn_lo);
                p[half][1] = __expf(sacc[nt][1] - mn_lo);
                p[half][2] = __expf(sacc[nt][2] - mn_hi);
                p[half][3] = __expf(sacc[nt][3] - mn_hi);
                sum_lo += p[half][0] + p[half][1];
                sum_hi += p[half][2] + p[half][3];
            }
            #pragma unroll
            for (int half = 0; half < 2; half++) {
                aph[kt2][0 + 2 * half] = pack_f16(__float2half_rn(p[half][0]),
                                                  __float2half_rn(p[half][1]));
                aph[kt2][1 + 2 * half] = pack_f16(__float2half_rn(p[half][2]),
                                                  __float2half_rn(p[half][3]));
            }
        }
        #pragma unroll
        for (int off = 1; off < 4; off <<= 1) {
            sum_lo += __shfl_xor_sync(0xffffffffu, sum_lo, off);
            sum_hi += __shfl_xor_sync(0xffffffffu, sum_hi, off);
        }
        l_lo = l_lo * al_lo + sum_lo;
        l_hi = l_hi * al_hi + sum_hi;
        #pragma unroll
        for (int dt = 0; dt < 16; dt++) {
            o[dt][0] *= al_lo; o[dt][1] *= al_lo;
            o[dt][2] *= al_hi; o[dt][3] *= al_hi;
        }

        // ---- O += P V (1-pass fp16) ----
        #pragma unroll
        for (int kt2 = 0; kt2 < 4; kt2++) {
            #pragma unroll
            for (int dp = 0; dp < 8; dp++) {
                uint32_t vh[4];
                const uint32_t vo = offkv(kt2 * 16 + v_r, 2 * dp + v_co);
                ldsm4t(vh[0], vh[1], vh[2], vh[3], stb + VH_OFF + vo);
                #pragma unroll
                for (int d2 = 0; d2 < 2; d2++) {
                    const int dt = 2 * dp + d2;
                    uint32_t bh[2] = { vh[d2 * 2], vh[d2 * 2 + 1] };
                    mma_f16(o[dt], aph[kt2], bh);
                }
            }
        }
    }

    // ---- epilogue: normalize + split-fp16 store ----
    const float inv_lo = 1.f / l_lo;
    const float inv_hi = 1.f / l_hi;
    const size_t ro_lo = ((size_t)(tb + row_lo) * NH + h) * HD;
    const size_t ro_hi = ro_lo + (size_t)8 * NH * HD;
    #pragma unroll
    for (int dt = 0; dt < 16; dt++) {
        const int c = dt * 8 + col_l;
        float f0 = o[dt][0] * inv_lo, f1 = o[dt][1] * inv_lo;
        float f2 = o[dt][2] * inv_hi, f3 = o[dt][3] * inv_hi;
        __half h0, l0, h1, l1, h2, l2, h3, l3;
        split_f16(f0, h0, l0);
        split_f16(f1, h1, l1);
        split_f16(f2, h2, l2);
        split_f16(f3, h3, l3);
        *(uint32_t*)(g_oh + ro_lo + c) = pack_f16(h0, h1);
        *(uint32_t*)(g_ol + ro_lo + c) = pack_f16(l0, l1);
        *(uint32_t*)(g_oh + ro_hi + c) = pack_f16(h2, h3);
        *(uint32_t*)(g_ol + ro_hi + c) = pack_f16(l2, l3);
    }
}

// ---------------- launch ----------------------------------------------------
extern "C" void kernel_launch(void* const* d_in, const int* in_sizes, int n_in,
                              void* d_out, int out_size)
{
    const float* x    = (const float*)d_in[0];
    const float* fcos = (const float*)d_in[2];
    const float* fsin = (const float*)d_in[3];
    const float* wq   = (const float*)d_in[6];
    const float* wk   = (const float*)d_in[7];
    const float* wv   = (const float*)d_in[8];
    const float* wo   = (const float*)d_in[9];
    float* out        = (float*)d_out;

    __half *xh, *xl, *oh, *ol, *wqkv, *wot;
    cudaGetSymbolAddress((void**)&xh, g_xh);
    cudaGetSymbolAddress((void**)&xl, g_xl);
    cudaGetSymbolAddress((void**)&oh, g_oh);
    cudaGetSymbolAddress((void**)&ol, g_ol);
    cudaGetSymbolAddress((void**)&wqkv, g_wqkv);
    cudaGetSymbolAddress((void**)&wot, g_wot);

    cudaFuncSetAttribute(gemm_hmma<0>, cudaFuncAttributeMaxDynamicSharedMemorySize, GEMM_SMEM);
    cudaFuncSetAttribute(gemm_hmma<1>, cudaFuncAttributeMaxDynamicSharedMemorySize, GEMM_SMEM);
    cudaFuncSetAttribute(attn_hmma, cudaFuncAttributeMaxDynamicSharedMemorySize, ATTN_SMEM);

    // launch 1: x split
    conv_split_kernel<<<(T_ * DIM / 4 + 255) / 256, 256>>>(x, xh, xl, T_ * DIM / 4);
    // launch 2: all weights transposed+converted in one kernel
    wconv_all_kernel<<<dim3(NWALL / 32, DIM / 32), dim3(32, 8)>>>(wq, wk, wv, wo);

    // launch 3: fused QKV projection + RoPE + scale + fp16 split
    gemm_hmma<1><<<dim3(NQKV / 256, T_ / 128), 512, GEMM_SMEM>>>(
        xh, xl, wqkv, out, NQKV, fcos, fsin);

    // launch 4 (profiled): attention
    attn_hmma<<<dim3(S_ / 128, NH, B_), 256, ATTN_SMEM>>>();

    // launch 5: output projection
    gemm_hmma<0><<<dim3(DIM / 256, T_ / 128), 512, GEMM_SMEM>>>(
        oh, ol, wot, out, DIM, fcos, fsin);
}

// round 16
// speedup vs baseline: 1.0244x; 1.0244x over previous
#include <cuda_runtime.h>
#include <cuda_fp16.h>
#include <cstdint>
#include <math.h>

#define DIM 4096
#define NH  32
#define NKV 8
#define HD  128
#define B_  2
#define S_  2048
#define T_  (B_*S_)          // 4096 tokens
#define NREP 4
#define NQKV 6144            // NH*HD + 2*NKV*HD
#define NWALL 10240          // NQKV + DIM (all weights)

// ---------------- scratch (device globals; no cudaMalloc allowed) ----------
__device__ __half g_xh[(size_t)T_ * DIM];
__device__ __half g_xl[(size_t)T_ * DIM];
__device__ __half g_oh[(size_t)T_ * DIM];
__device__ __half g_ol[(size_t)T_ * DIM];
__device__ __half g_qh[(size_t)T_ * NH * HD];
__device__ __half g_ql[(size_t)T_ * NH * HD];
__device__ __half g_kh[(size_t)T_ * NKV * HD];
__device__ __half g_kl[(size_t)T_ * NKV * HD];
__device__ __half g_vh[(size_t)T_ * NKV * HD];
__device__ __half g_wqkv[(size_t)NQKV * DIM];   // [wq | wk | wv] transposed
__device__ __half g_wot[(size_t)DIM * DIM];

// ---------------- low-level helpers (sm_103 base-target safe) --------------
__device__ __forceinline__ uint32_t smem_u32(const void* p) {
    uint32_t a;
    asm("{ .reg .u64 t; cvta.to.shared.u64 t, %1; cvt.u32.u64 %0, t; }"
        : "=r"(a) : "l"(p));
    return a;
}
__device__ __forceinline__ void cp_async16(uint32_t dst, const void* src) {
    asm volatile("cp.async.cg.shared.global [%0], [%1], 16;"
                 :: "r"(dst), "l"(src));
}
#define CP_COMMIT() asm volatile("cp.async.commit_group;" ::: "memory")
#define CP_WAIT(n)  asm volatile("cp.async.wait_group %0;" :: "n"(n) : "memory")

__device__ __forceinline__ void ldsm4(uint32_t& r0, uint32_t& r1,
                                      uint32_t& r2, uint32_t& r3, uint32_t a) {
    asm volatile("ldmatrix.sync.aligned.m8n8.x4.shared.b16 {%0,%1,%2,%3}, [%4];"
                 : "=r"(r0), "=r"(r1), "=r"(r2), "=r"(r3) : "r"(a));
}
__device__ __forceinline__ void ldsm4t(uint32_t& r0, uint32_t& r1,
                                       uint32_t& r2, uint32_t& r3, uint32_t a) {
    asm volatile("ldmatrix.sync.aligned.m8n8.x4.trans.shared.b16 {%0,%1,%2,%3}, [%4];"
                 : "=r"(r0), "=r"(r1), "=r"(r2), "=r"(r3) : "r"(a));
}
__device__ __forceinline__ void mma_f16(float* c, const uint32_t* a,
                                        const uint32_t* b) {
    asm volatile(
        "mma.sync.aligned.m16n8k16.row.col.f32.f16.f16.f32 "
        "{%0,%1,%2,%3}, {%4,%5,%6,%7}, {%8,%9}, {%0,%1,%2,%3};"
        : "+f"(c[0]), "+f"(c[1]), "+f"(c[2]), "+f"(c[3])
        : "r"(a[0]), "r"(a[1]), "r"(a[2]), "r"(a[3]), "r"(b[0]), "r"(b[1]));
}

// ---------------- split-fp16 conversion -------------------------------------
__device__ __forceinline__ void split_f16(float x, __half& h, __half& l)
{
    h = __float2half_rn(x);
    l = __float2half_rn(x - __half2float(h));
}
__device__ __forceinline__ uint32_t pack_f16(__half lo, __half hi)
{
    __half2 v;
    v.x = lo; v.y = hi;
    return *(uint32_t*)&v;
}

__global__ void conv_split_kernel(const float* __restrict__ X,
                                  __half* __restrict__ H,
                                  __half* __restrict__ L, int n4)
{
    int i = blockIdx.x * blockDim.x + threadIdx.x;
    if (i >= n4) return;
    float4 v = *(const float4*)(X + (size_t)i * 4);
    __half h[4], l[4];
    split_f16(v.x, h[0], l[0]);
    split_f16(v.y, h[1], l[1]);
    split_f16(v.z, h[2], l[2]);
    split_f16(v.w, h[3], l[3]);
    *(uint2*)(H + (size_t)i * 4) = *(uint2*)h;
    *(uint2*)(L + (size_t)i * 4) = *(uint2*)l;
}

// merged transpose+convert of wq|wk|wv|wo into g_wqkv / g_wot (one launch)
__global__ void wconv_all_kernel(const float* __restrict__ wq,
                                 const float* __restrict__ wk,
                                 const float* __restrict__ wv,
                                 const float* __restrict__ wo)
{
    __shared__ float t[32][33];
    const int c0 = blockIdx.x * 32;   // combined column tile (0..NWALL-1)
    const int k0 = blockIdx.y * 32;
    const int tx = threadIdx.x;
    const int ty = threadIdx.y;

    const float* W;
    __half* Hd;
    int nloc, Nsrc, dcol;
    if (c0 < NH * HD) {
        W = wq; nloc = c0; Nsrc = NH * HD; Hd = g_wqkv; dcol = c0;
    } else if (c0 < NH * HD + NKV * HD) {
        W = wk; nloc = c0 - NH * HD; Nsrc = NKV * HD; Hd = g_wqkv; dcol = c0;
    } else if (c0 < NQKV) {
        W = wv; nloc = c0 - NH * HD - NKV * HD; Nsrc = NKV * HD; Hd = g_wqkv; dcol = c0;
    } else {
        W = wo; nloc = c0 - NQKV; Nsrc = DIM; Hd = g_wot; dcol = c0 - NQKV;
    }

    #pragma unroll
    for (int i = 0; i < 4; i++)
        t[ty + 8 * i][tx] = W[(size_t)(k0 + ty + 8 * i) * Nsrc + nloc + tx];
    __syncthreads();
    #pragma unroll
    for (int i = 0; i < 4; i++) {
        float v = t[tx][ty + 8 * i];
        Hd[(size_t)(dcol + ty + 8 * i) * DIM + k0 + tx] = __float2half_rn(v);
    }
}

// ---------------- HMMA 2-pass split-fp16 GEMM (128x256, BK=64, 3-stage) ----
#define GK       DIM
#define NCH2     (GK / 64)          // 32 double-chunks
#define A_H_OFF  0
#define A_L_OFF  16384
#define B_OFF    32768
#define STAGEB   65536              // Ah(16K) + Al(16K) + B(32K)
#define GEMM_SMEM (3 * STAGEB)      // 192 KB

__device__ __forceinline__ uint32_t chunk_offA(int row, int kg) {
    return (uint32_t)(kg * 128 + ((row + 2 * kg) & 127)) * 16u;
}
__device__ __forceinline__ uint32_t chunk_offB(int row, int kg) {
    return (uint32_t)(kg * 256 + ((row + 2 * kg) & 255)) * 16u;
}

#define ATT_SCALE 0.08838834764831843f   // 1/sqrt(128), folded into Q

template<int MODE>
__global__ __launch_bounds__(512, 1) void gemm_hmma(
    const __half* __restrict__ Ah, const __half* __restrict__ Al,
    const __half* __restrict__ B,
    float* __restrict__ C, int N,
    const float* __restrict__ fcos, const float* __restrict__ fsin)
{
    extern __shared__ char smg[];
    const uint32_t sbase = smem_u32(smg);

    const int tid = threadIdx.x;
    const int wid = tid >> 5;
    const int lid = tid & 31;
    const int wm  = wid >> 2;      // 0..3 (32 rows each)
    const int wn  = wid & 3;       // 0..3 (64 cols each)
    const int m0  = blockIdx.y * 128;
    const int n0  = blockIdx.x * 256;

    const int lkg = tid & 7;       // 0..7 (16B k-group within BK=64)
    const int lr  = tid >> 3;      // 0..63

    auto load_stage = [&](int stage, int kc2) {
        const uint32_t sb = sbase + stage * STAGEB;
        const size_t koff = (size_t)kc2 * 64 + lkg * 8;
        #pragma unroll
        for (int i = 0; i < 2; i++) {
            const int r = lr + i * 64;
            const uint32_t co = chunk_offA(r, lkg);
            const size_t ga = (size_t)(m0 + r) * GK + koff;
            cp_async16(sb + A_H_OFF + co, Ah + ga);
            cp_async16(sb + A_L_OFF + co, Al + ga);
        }
        #pragma unroll
        for (int i = 0; i < 4; i++) {
            const int r = lr + i * 64;
            const uint32_t co = chunk_offB(r, lkg);
            const size_t gb = (size_t)(n0 + r) * GK + koff;
            cp_async16(sb + B_OFF + co, B + gb);
        }
    };

    float acc[2][8][4];
    #pragma unroll
    for (int i = 0; i < 2; i++)
        #pragma unroll
        for (int j = 0; j < 8; j++)
            #pragma unroll
            for (int k = 0; k < 4; k++) acc[i][j][k] = 0.f;

    const int sel  = lid >> 3;
    const int lsub = lid & 7;
    const int a_mo = lsub + ((sel & 1) << 3);
    const int a_kg = sel >> 1;
    const int b_no = lsub + ((sel >> 1) << 3);
    const int b_kg = sel & 1;

    load_stage(0, 0); CP_COMMIT();
    load_stage(1, 1); CP_COMMIT();

    for (int kc2 = 0; kc2 < NCH2; kc2++) {
        CP_WAIT(1);              // stage kc2 complete (kc2+1 may be in flight)
        __syncthreads();         // visibility + all readers of kc2-1 done

        if (kc2 + 2 < NCH2) load_stage((kc2 + 2) % 3, kc2 + 2);
        CP_COMMIT();             // keeps group arithmetic uniform

        const uint32_t sb = sbase + (kc2 % 3) * STAGEB;

        #pragma unroll
        for (int ks = 0; ks < 4; ks++) {
            const int kgA = ks * 2 + a_kg;
            const int kgB = ks * 2 + b_kg;

            uint32_t afh[2][4], afl[2][4];
            #pragma unroll
            for (int mt = 0; mt < 2; mt++) {
                const int m = wm * 32 + mt * 16 + a_mo;
                const uint32_t co = chunk_offA(m, kgA);
                ldsm4(afh[mt][0], afh[mt][1], afh[mt][2], afh[mt][3],
                      sb + A_H_OFF + co);
                ldsm4(afl[mt][0], afl[mt][1], afl[mt][2], afl[mt][3],
                      sb + A_L_OFF + co);
            }
            uint32_t bf[4][4];
            #pragma unroll
            for (int nt2 = 0; nt2 < 4; nt2++) {
                const int n = wn * 64 + nt2 * 16 + b_no;
                const uint32_t co = chunk_offB(n, kgB);
                ldsm4(bf[nt2][0], bf[nt2][1], bf[nt2][2], bf[nt2][3],
                      sb + B_OFF + co);
            }
            #pragma unroll
            for (int mt = 0; mt < 2; mt++)
                #pragma unroll
                for (int nt = 0; nt < 8; nt++) {
                    uint32_t b2[2] = { bf[nt >> 1][(nt & 1) << 1],
                                       bf[nt >> 1][((nt & 1) << 1) + 1] };
                    mma_f16(acc[mt][nt], afh[mt], b2);
                    mma_f16(acc[mt][nt], afl[mt], b2);
                }
        }
    }

    const int crow = lid >> 2;
    const int ccol = (lid & 3) * 2;

    if (MODE == 0) {
        #pragma unroll
        for (int mt = 0; mt < 2; mt++) {
            const int r0 = m0 + wm * 32 + mt * 16 + crow;
            #pragma unroll
            for (int nt = 0; nt < 8; nt++) {
                const int c0 = n0 + wn * 64 + nt * 8 + ccol;
                *(float2*)(C + (size_t)r0 * N + c0) =
                    make_float2(acc[mt][nt][0], acc[mt][nt][1]);
                *(float2*)(C + (size_t)(r0 + 8) * N + c0) =
                    make_float2(acc[mt][nt][2], acc[mt][nt][3]);
            }
        }
    } else {
        // fused RoPE + 1/sqrt(d) (Q only) + split-fp16 QKV epilogue
        const int seg = (n0 < NH * HD) ? 0 : (n0 < NH * HD + NKV * HD ? 1 : 2);
        __half* Hd;
        __half* Ld = nullptr;
        int colbase, rstride;
        if (seg == 0)      { Hd = g_qh; Ld = g_ql; colbase = n0;                rstride = NH * HD;  }
        else if (seg == 1) { Hd = g_kh; Ld = g_kl; colbase = n0 - NH * HD;      rstride = NKV * HD; }
        else               { Hd = g_vh;            colbase = n0 - NH * HD - NKV * HD; rstride = NKV * HD; }

        #pragma unroll
        for (int mt = 0; mt < 2; mt++) {
            const int r0 = m0 + wm * 32 + mt * 16 + crow;
            const int r1 = r0 + 8;
            const int s0 = r0 & (S_ - 1);
            const int s1 = r1 & (S_ - 1);
            #pragma unroll
            for (int nt = 0; nt < 8; nt++) {
                const int c = colbase + wn * 64 + nt * 8 + ccol;
                float v00 = acc[mt][nt][0], v01 = acc[mt][nt][1];
                float v10 = acc[mt][nt][2], v11 = acc[mt][nt][3];
                if (seg < 2) {
                    const int d = (c & (HD - 1)) >> 1;
                    const float c0v = fcos[s0 * (HD / 2) + d];
                    const float s0v = fsin[s0 * (HD / 2) + d];
                    const float c1v = fcos[s1 * (HD / 2) + d];
                    const float s1v = fsin[s1 * (HD / 2) + d];
                    float t00 = v00 * c0v - v01 * s0v;
                    float t01 = v00 * s0v + v01 * c0v;
                    float t10 = v10 * c1v - v11 * s1v;
                    float t11 = v10 * s1v + v11 * c1v;
                    v00 = t00; v01 = t01; v10 = t10; v11 = t11;
                    if (seg == 0) {
                        v00 *= ATT_SCALE; v01 *= ATT_SCALE;
                        v10 *= ATT_SCALE; v11 *= ATT_SCALE;
                    }
                }
                const size_t o0 = (size_t)r0 * rstride + c;
                const size_t o1 = (size_t)r1 * rstride + c;
                __half h0, l0, h1, l1;
                split_f16(v00, h0, l0);
                split_f16(v01, h1, l1);
                *(uint32_t*)(Hd + o0) = pack_f16(h0, h1);
                if (seg < 2) *(uint32_t*)(Ld + o0) = pack_f16(l0, l1);
                split_f16(v10, h0, l0);
                split_f16(v11, h1, l1);
                *(uint32_t*)(Hd + o1) = pack_f16(h0, h1);
                if (seg < 2) *(uint32_t*)(Ld + o1) = pack_f16(l0, l1);
            }
        }
    }
}

// ---------------- HMMA split-fp16 flash attention ---------------------------
// CTA: 128 q rows x one (b, head). 3-stage KV ring, ONE sync per tile.
// Q cached in registers; 1/sqrt(d) pre-folded into Q.
#define SQH_OFF 0
#define SQL_OFF 32768
#define STG_OFF 65536
#define STG_SZ  49152              // Kh + Kl + Vh
#define KH_OFF  0
#define KL_OFF  16384
#define VH_OFF  32768
#define ATTN_SMEM (STG_OFF + 3 * STG_SZ)   // 208 KB

__device__ __forceinline__ uint32_t offq(int r, int c) {
    return (uint32_t)(c * 128 + ((r + 2 * c) & 127)) * 16u;
}
__device__ __forceinline__ uint32_t offkv(int r, int c) {
    return (uint32_t)(c * 64 + ((r + 2 * c) & 63)) * 16u;
}

__global__ __launch_bounds__(256, 1) void attn_hmma()
{
    extern __shared__ char sma[];
    const uint32_t sb = smem_u32(sma);

    const int tid = threadIdx.x;
    const int wid = tid >> 5;
    const int lid = tid & 31;
    const int bx  = gridDim.x - 1 - blockIdx.x;   // LPT: longest CTAs first
    const int h   = blockIdx.y;
    const int bz  = blockIdx.z;
    const int g   = h >> 2;
    const int qm0 = bx * 128;
    const int tb  = bz * S_;
    const int ntiles = 2 * (bx + 1);

    const int sel  = lid >> 3;
    const int lsub = lid & 7;
    const int a_r  = wid * 16 + lsub + ((sel & 1) << 3);
    const int a_co = sel >> 1;
    const int b_r  = lsub + ((sel >> 1) << 3);
    const int b_co = sel & 1;
    const int v_r  = lsub + ((sel & 1) << 3);
    const int v_co = sel >> 1;

    const int lc = tid & 15;
    const int lr = tid >> 4;

    // group 0: Q + kv tile 0
    {
        #pragma unroll
        for (int i = 0; i < 8; i++) {
            const int r = lr + 16 * i;
            const size_t go = ((size_t)(tb + qm0 + r) * NH + h) * HD + lc * 8;
            const uint32_t o = offq(r, lc);
            cp_async16(sb + SQH_OFF + o, g_qh + go);
            cp_async16(sb + SQL_OFF + o, g_ql + go);
        }
    }
    auto load_kv = [&](int stage, int t) {
        const uint32_t st = sb + STG_OFF + stage * STG_SZ;
        const int j0 = t * 64;
        #pragma unroll
        for (int i = 0; i < 4; i++) {
            const int r = lr + 16 * i;
            const size_t go = ((size_t)(tb + j0 + r) * NKV + g) * HD + lc * 8;
            const uint32_t o = offkv(r, lc);
            cp_async16(st + KH_OFF + o, g_kh + go);
            cp_async16(st + KL_OFF + o, g_kl + go);
            cp_async16(st + VH_OFF + o, g_vh + go);
        }
    };

    load_kv(0, 0); CP_COMMIT();                // group 0: Q + tile0
    load_kv(1, 1); CP_COMMIT();                // group 1: tile1 (ntiles >= 2)

    // wait for Q + tile0, cache Q fragments in registers
    CP_WAIT(1);
    __syncthreads();
    uint32_t qfh[8][4], qfl[8][4];
    #pragma unroll
    for (int kt = 0; kt < 8; kt++) {
        const uint32_t qo = offq(a_r, 2 * kt + a_co);
        ldsm4(qfh[kt][0], qfh[kt][1], qfh[kt][2], qfh[kt][3], sb + SQH_OFF + qo);
        ldsm4(qfl[kt][0], qfl[kt][1], qfl[kt][2], qfl[kt][3], sb + SQL_OFF + qo);
    }

    float o[16][4];
    #pragma unroll
    for (int i = 0; i < 16; i++)
        #pragma unroll
        for (int j = 0; j < 4; j++) o[i][j] = 0.f;
    float m_lo = -1e30f, m_hi = -1e30f;
    float l_lo = 0.f, l_hi = 0.f;
    const int row_lo = qm0 + wid * 16 + (lid >> 2);
    const int col_l  = (lid & 3) * 2;

    for (int t = 0; t < ntiles; t++) {
        if (t > 0) {
            CP_WAIT(1);          // group t complete (group t+1 may be in flight)
            __syncthreads();     // visibility + readers of tile t-1 done
        }

        // prefetch tile t+2 into stage (t+2)%3 == (t-1)%3 (readers done)
        if (t + 2 < ntiles) load_kv((t + 2) % 3, t + 2);
        CP_COMMIT();             // uniform group count

        const uint32_t stb = sb + STG_OFF + (t % 3) * STG_SZ;
        const bool masked = (t >= 2 * bx);
        const int j0 = t * 64;

        // ---- S = Q K^T (3-pass fp16; scale pre-folded into Q) ----
        float sacc[8][4];
        #pragma unroll
        for (int i = 0; i < 8; i++)
            #pragma unroll
            for (int j = 0; j < 4; j++) sacc[i][j] = 0.f;

        #pragma unroll
        for (int kt = 0; kt < 8; kt++) {
            uint32_t kh[4][4], kl[4][4];
            #pragma unroll
            for (int np = 0; np < 4; np++) {
                const uint32_t ko = offkv(np * 16 + b_r, 2 * kt + b_co);
                ldsm4(kh[np][0], kh[np][1], kh[np][2], kh[np][3],
                      stb + KH_OFF + ko);
                ldsm4(kl[np][0], kl[np][1], kl[np][2], kl[np][3],
                      stb + KL_OFF + ko);
            }
            #pragma unroll
            for (int nt = 0; nt < 8; nt++) {
                uint32_t bh[2] = { kh[nt >> 1][(nt & 1) << 1],
                                   kh[nt >> 1][((nt & 1) << 1) + 1] };
                uint32_t bl[2] = { kl[nt >> 1][(nt & 1) << 1],
                                   kl[nt >> 1][((nt & 1) << 1) + 1] };
                mma_f16(sacc[nt], qfh[kt], bh);
                mma_f16(sacc[nt], qfl[kt], bh);
                mma_f16(sacc[nt], qfh[kt], bl);
            }
        }

        // ---- causal mask (scale already applied via Q) ----
        if (masked) {
            #pragma unroll
            for (int nt = 0; nt < 8; nt++) {
                const int c0 = j0 + nt * 8 + col_l;
                sacc[nt][0] = (c0     <= row_lo)     ? sacc[nt][0] : -1e30f;
                sacc[nt][1] = (c0 + 1 <= row_lo)     ? sacc[nt][1] : -1e30f;
                sacc[nt][2] = (c0     <= row_lo + 8) ? sacc[nt][2] : -1e30f;
                sacc[nt][3] = (c0 + 1 <= row_lo + 8) ? sacc[nt][3] : -1e30f;
            }
        }

        // ---- online softmax ----
        float mx_lo = -1e30f, mx_hi = -1e30f;
        #pragma unroll
        for (int nt = 0; nt < 8; nt++) {
            mx_lo = fmaxf(mx_lo, fmaxf(sacc[nt][0], sacc[nt][1]));
            mx_hi = fmaxf(mx_hi, fmaxf(sacc[nt][2], sacc[nt][3]));
        }
        #pragma unroll
        for (int off = 1; off < 4; off <<= 1) {
            mx_lo = fmaxf(mx_lo, __shfl_xor_sync(0xffffffffu, mx_lo, off));
            mx_hi = fmaxf(mx_hi, __shfl_xor_sync(0xffffffffu, mx_hi, off));
        }
        const float mn_lo = fmaxf(m_lo, mx_lo);
        const float mn_hi = fmaxf(m_hi, mx_hi);
        const float al_lo = __expf(m_lo - mn_lo);
        const float al_hi = __expf(m_hi - mn_hi);
        m_lo = mn_lo; m_hi = mn_hi;

        float sum_lo = 0.f, sum_hi = 0.f;
        uint32_t aph[4][4];
        #pragma unroll
        for (int kt2 = 0; kt2 < 4; kt2++) {
            float p[2][4];
            #pragma unroll
            for (int half = 0; half < 2; half++) {
                const int nt = 2 * kt2 + half;
                p[half][0] = __expf(sacc[nt][0] - mn_lo);
                p[half][1] = __expf(sacc[nt][1] - mn_lo);
                p[half][2] = __expf(sacc[nt][2] - mn_hi);
                p[half][3] = __expf(sacc[nt][3] - mn_hi);
                sum_lo += p[half][0] + p[half][1];
                sum_hi += p[half][2] + p[half][3];
            }
            #pragma unroll
            for (int half = 0; half < 2; half++) {
                aph[kt2][0 + 2 * half] = pack_f16(__float2half_rn(p[half][0]),
                                                  __float2half_rn(p[half][1]));
                aph[kt2][1 + 2 * half] = pack_f16(__float2half_rn(p[half][2]),
                                                  __float2half_rn(p[half][3]));
            }
        }
        #pragma unroll
        for (int off = 1; off < 4; off <<= 1) {
            sum_lo += __shfl_xor_sync(0xffffffffu, sum_lo, off);
            sum_hi += __shfl_xor_sync(0xffffffffu, sum_hi, off);
        }
        l_lo = l_lo * al_lo + sum_lo;
        l_hi = l_hi * al_hi + sum_hi;
        #pragma unroll
        for (int dt = 0; dt < 16; dt++) {
            o[dt][0] *= al_lo; o[dt][1] *= al_lo;
            o[dt][2] *= al_hi; o[dt][3] *= al_hi;
        }

        // ---- O += P V (1-pass fp16) ----
        #pragma unroll
        for (int kt2 = 0; kt2 < 4; kt2++) {
            #pragma unroll
            for (int dp = 0; dp < 8; dp++) {
                uint32_t vh[4];
                const uint32_t vo = offkv(kt2 * 16 + v_r, 2 * dp + v_co);
                ldsm4t(vh[0], vh[1], vh[2], vh[3], stb + VH_OFF + vo);
                #pragma unroll
                for (int d2 = 0; d2 < 2; d2++) {
                    const int dt = 2 * dp + d2;
                    uint32_t bh[2] = { vh[d2 * 2], vh[d2 * 2 + 1] };
                    mma_f16(o[dt], aph[kt2], bh);
                }
            }
        }
    }

    // ---- epilogue: normalize + split-fp16 store ----
    const float inv_lo = 1.f / l_lo;
    const float inv_hi = 1.f / l_hi;
    const size_t ro_lo = ((size_t)(tb + row_lo) * NH + h) * HD;
    const size_t ro_hi = ro_lo + (size_t)8 * NH * HD;
    #pragma unroll
    for (int dt = 0; dt < 16; dt++) {
        const int c = dt * 8 + col_l;
        float f0 = o[dt][0] * inv_lo, f1 = o[dt][1] * inv_lo;
        float f2 = o[dt][2] * inv_hi, f3 = o[dt][3] * inv_hi;
        __half h0, l0, h1, l1, h2, l2, h3, l3;
        split_f16(f0, h0, l0);
        split_f16(f1, h1, l1);
        split_f16(f2, h2, l2);
        split_f16(f3, h3, l3);
        *(uint32_t*)(g_oh + ro_lo + c) = pack_f16(h0, h1);
        *(uint32_t*)(g_ol + ro_lo + c) = pack_f16(l0, l1);
        *(uint32_t*)(g_oh + ro_hi + c) = pack_f16(h2, h3);
        *(uint32_t*)(g_ol + ro_hi + c) = pack_f16(l2, l3);
    }
}

// ---------------- launch ----------------------------------------------------
extern "C" void kernel_launch(void* const* d_in, const int* in_sizes, int n_in,
                              void* d_out, int out_size)
{
    const float* x    = (const float*)d_in[0];
    const float* fcos = (const float*)d_in[2];
    const float* fsin = (const float*)d_in[3];
    const float* wq   = (const float*)d_in[6];
    const float* wk   = (const float*)d_in[7];
    const float* wv   = (const float*)d_in[8];
    const float* wo   = (const float*)d_in[9];
    float* out        = (float*)d_out;

    __half *xh, *xl, *oh, *ol, *wqkv, *wot;
    cudaGetSymbolAddress((void**)&xh, g_xh);
    cudaGetSymbolAddress((void**)&xl, g_xl);
    cudaGetSymbolAddress((void**)&oh, g_oh);
    cudaGetSymbolAddress((void**)&ol, g_ol);
    cudaGetSymbolAddress((void**)&wqkv, g_wqkv);
    cudaGetSymbolAddress((void**)&wot, g_wot);

    cudaFuncSetAttribute(gemm_hmma<0>, cudaFuncAttributeMaxDynamicSharedMemorySize, GEMM_SMEM);
    cudaFuncSetAttribute(gemm_hmma<1>, cudaFuncAttributeMaxDynamicSharedMemorySize, GEMM_SMEM);
    cudaFuncSetAttribute(attn_hmma, cudaFuncAttributeMaxDynamicSharedMemorySize, ATTN_SMEM);

    // launch 1: x split
    conv_split_kernel<<<(T_ * DIM / 4 + 255) / 256, 256>>>(x, xh, xl, T_ * DIM / 4);
    // launch 2: all weights transposed+converted in one kernel
    wconv_all_kernel<<<dim3(NWALL / 32, DIM / 32), dim3(32, 8)>>>(wq, wk, wv, wo);

    // launch 3: fused QKV projection + RoPE + scale + fp16 split
    gemm_hmma<1><<<dim3(NQKV / 256, T_ / 128), 512, GEMM_SMEM>>>(
        xh, xl, wqkv, out, NQKV, fcos, fsin);

    // launch 4 (profiled): attention
    attn_hmma<<<dim3(S_ / 128, NH, B_), 256, ATTN_SMEM>>>();

    // launch 5: output projection
    gemm_hmma<0><<<dim3(DIM / 256, T_ / 128), 512, GEMM_SMEM>>>(
        oh, ol, wot, out, DIM, fcos, fsin);
}